// round 4
// baseline (speedup 1.0000x reference)
#include <cuda_runtime.h>
#include <math.h>

// Problem constants (fixed by the dataset)
#define TT   4096          // tokens = B*S
#define HD   1024          // hidden
#define FD   4096          // ffn dim
#define NE   8             // experts
#define KSEL 2             // top-k
#define NSLOTS (TT * KSEL) // 8192 token-expert pairs

// ---------------- static scratch (no allocations allowed) ----------------
__device__ int   d_count[NE];
__device__ int   d_fill[NE];
__device__ int   d_offset[NE];
__device__ int   d_rows[NSLOTS];          // slot -> token
__device__ int   d_tope[TT * KSEL];       // token -> expert ids
__device__ int   d_slot[TT * KSEL];       // token -> slot ids
__device__ float d_wgt[TT * KSEL];        // token -> combine weights
__device__ float d_inter[(size_t)NSLOTS * FD];  // 128 MB: silu(x w1^T) * (x w3^T)
__device__ float d_y[(size_t)NSLOTS * HD];      // 32 MB: expert outputs per slot

// ---------------- kernels ----------------

__global__ void zero_counters_kernel() {
    int i = threadIdx.x;
    if (i < NE) { d_count[i] = 0; d_fill[i] = 0; }
}

// One block (256 thr = 8 warps) per token. Warp e computes logit for expert e.
__global__ void router_kernel(const float* __restrict__ x,
                              const float* __restrict__ gw,
                              float* __restrict__ logits_out) {
    int t    = blockIdx.x;
    int warp = threadIdx.x >> 5;
    int lane = threadIdx.x & 31;
    const float* xr = x + (size_t)t * HD;
    const float* gr = gw + (size_t)warp * HD;
    float s = 0.f;
    #pragma unroll 8
    for (int i = lane; i < HD; i += 32) s += xr[i] * gr[i];
    #pragma unroll
    for (int o = 16; o; o >>= 1) s += __shfl_xor_sync(0xffffffffu, s, o);
    __shared__ float sl[NE];
    if (lane == 0) sl[warp] = s;
    __syncthreads();
    if (threadIdx.x < NE) logits_out[(size_t)t * NE + threadIdx.x] = sl[threadIdx.x];
    if (threadIdx.x == 0) {
        float mx = sl[0];
        #pragma unroll
        for (int e = 1; e < NE; e++) mx = fmaxf(mx, sl[e]);
        float p[NE];
        #pragma unroll
        for (int e = 0; e < NE; e++) p[e] = expf(sl[e] - mx);
        // top-2 (first index wins ties, matching lax.top_k)
        int e0 = 0;
        #pragma unroll
        for (int e = 1; e < NE; e++) if (p[e] > p[e0]) e0 = e;
        int e1 = (e0 == 0) ? 1 : 0;
        #pragma unroll
        for (int e = 0; e < NE; e++) { if (e == e0) continue; if (p[e] > p[e1]) e1 = e; }
        float w0 = p[e0], w1 = p[e1];
        float ws = w0 + w1;
        w0 /= ws; w1 /= ws;
        d_tope[t * 2 + 0] = e0; d_tope[t * 2 + 1] = e1;
        d_wgt[t * 2 + 0] = w0;  d_wgt[t * 2 + 1] = w1;
        atomicAdd(&d_count[e0], 1);
        atomicAdd(&d_count[e1], 1);
    }
}

__global__ void offsets_kernel() {
    if (threadIdx.x == 0) {
        int acc = 0;
        #pragma unroll
        for (int e = 0; e < NE; e++) { d_offset[e] = acc; acc += d_count[e]; }
    }
}

__global__ void assign_kernel() {
    int t = blockIdx.x * blockDim.x + threadIdx.x;
    if (t >= TT) return;
    #pragma unroll
    for (int k = 0; k < KSEL; k++) {
        int e = d_tope[t * 2 + k];
        int pos = atomicAdd(&d_fill[e], 1);
        int s = d_offset[e] + pos;
        d_rows[s] = t;
        d_slot[t * 2 + k] = s;
    }
}

// ---- Tiled fp32 GEMM cores: 64x64 tile, K-step 16, 256 thr, 4x4 per thread ----
#define TM 64
#define TN 64
#define TKS 16

// GEMM1: inter[s][f] = silu(x[tok] . w1[e][f]) * (x[tok] . w3[e][f])
__global__ void __launch_bounds__(256, 3)
gemm1_kernel(const float* __restrict__ x,
             const float* __restrict__ w1,
             const float* __restrict__ w3) {
    int e  = blockIdx.z;
    int m0 = blockIdx.y * TM;
    int n0 = blockIdx.x * TN;
    int cnt = d_count[e];
    if (m0 >= cnt) return;
    int base = d_offset[e];

    __shared__ __align__(16) float As[TKS][TM];
    __shared__ __align__(16) float B1s[TKS][TN];
    __shared__ __align__(16) float B3s[TKS][TN];
    __shared__ int tok[TM];

    int tid = threadIdx.x;               // 0..255
    if (tid < TM) {
        int m = m0 + tid;
        tok[tid] = (m < cnt) ? d_rows[base + m] : d_rows[base];
    }
    __syncthreads();

    const float* W1 = w1 + (size_t)e * FD * HD;
    const float* W3 = w3 + (size_t)e * FD * HD;

    int lm  = tid & 63;    // row within tile for loading
    int lk  = (tid >> 6) * 4;  // k sub-offset 0,4,8,12
    int ty  = tid >> 4;    // 0..15
    int tx  = tid & 15;    // 0..15

    float acc1[4][4]; float acc3[4][4];
    #pragma unroll
    for (int i = 0; i < 4; i++)
        #pragma unroll
        for (int j = 0; j < 4; j++) { acc1[i][j] = 0.f; acc3[i][j] = 0.f; }

    const size_t xrow = (size_t)tok[lm] * HD;
    const size_t brow = (size_t)(n0 + lm) * HD;

    for (int k0 = 0; k0 < HD; k0 += TKS) {
        float4 av = *reinterpret_cast<const float4*>(x  + xrow + k0 + lk);
        float4 b1 = *reinterpret_cast<const float4*>(W1 + brow + k0 + lk);
        float4 b3 = *reinterpret_cast<const float4*>(W3 + brow + k0 + lk);
        As [lk + 0][lm] = av.x; As [lk + 1][lm] = av.y; As [lk + 2][lm] = av.z; As [lk + 3][lm] = av.w;
        B1s[lk + 0][lm] = b1.x; B1s[lk + 1][lm] = b1.y; B1s[lk + 2][lm] = b1.z; B1s[lk + 3][lm] = b1.w;
        B3s[lk + 0][lm] = b3.x; B3s[lk + 1][lm] = b3.y; B3s[lk + 2][lm] = b3.z; B3s[lk + 3][lm] = b3.w;
        __syncthreads();
        #pragma unroll
        for (int kk = 0; kk < TKS; kk++) {
            float4 a  = *reinterpret_cast<const float4*>(&As [kk][ty * 4]);
            float4 p1 = *reinterpret_cast<const float4*>(&B1s[kk][tx * 4]);
            float4 p3 = *reinterpret_cast<const float4*>(&B3s[kk][tx * 4]);
            float aa[4] = {a.x, a.y, a.z, a.w};
            float b1v[4] = {p1.x, p1.y, p1.z, p1.w};
            float b3v[4] = {p3.x, p3.y, p3.z, p3.w};
            #pragma unroll
            for (int i = 0; i < 4; i++)
                #pragma unroll
                for (int j = 0; j < 4; j++) {
                    acc1[i][j] += aa[i] * b1v[j];
                    acc3[i][j] += aa[i] * b3v[j];
                }
        }
        __syncthreads();
    }

    #pragma unroll
    for (int i = 0; i < 4; i++) {
        int m = m0 + ty * 4 + i;
        if (m < cnt) {
            float4 o;
            float v;
            v = acc1[i][0]; o.x = (v / (1.f + expf(-v))) * acc3[i][0];
            v = acc1[i][1]; o.y = (v / (1.f + expf(-v))) * acc3[i][1];
            v = acc1[i][2]; o.z = (v / (1.f + expf(-v))) * acc3[i][2];
            v = acc1[i][3]; o.w = (v / (1.f + expf(-v))) * acc3[i][3];
            *reinterpret_cast<float4*>(&d_inter[(size_t)(base + m) * FD + n0 + tx * 4]) = o;
        }
    }
}

// GEMM2: y[s][h] = inter[s] . w2[e][h]   (K = FD)
__global__ void __launch_bounds__(256, 3)
gemm2_kernel(const float* __restrict__ w2) {
    int e  = blockIdx.z;
    int m0 = blockIdx.y * TM;
    int n0 = blockIdx.x * TN;
    int cnt = d_count[e];
    if (m0 >= cnt) return;
    int base = d_offset[e];

    __shared__ __align__(16) float As[TKS][TM];
    __shared__ __align__(16) float Bs[TKS][TN];

    int tid = threadIdx.x;
    int lm  = tid & 63;
    int lk  = (tid >> 6) * 4;
    int ty  = tid >> 4;
    int tx  = tid & 15;

    int mrow = m0 + lm;
    size_t arow = (size_t)((mrow < cnt) ? (base + mrow) : base) * FD;
    const float* W2 = w2 + (size_t)e * HD * FD;
    size_t brow = (size_t)(n0 + lm) * FD;

    float acc[4][4];
    #pragma unroll
    for (int i = 0; i < 4; i++)
        #pragma unroll
        for (int j = 0; j < 4; j++) acc[i][j] = 0.f;

    for (int k0 = 0; k0 < FD; k0 += TKS) {
        float4 av = *reinterpret_cast<const float4*>(&d_inter[arow + k0 + lk]);
        float4 bv = *reinterpret_cast<const float4*>(W2 + brow + k0 + lk);
        As[lk + 0][lm] = av.x; As[lk + 1][lm] = av.y; As[lk + 2][lm] = av.z; As[lk + 3][lm] = av.w;
        Bs[lk + 0][lm] = bv.x; Bs[lk + 1][lm] = bv.y; Bs[lk + 2][lm] = bv.z; Bs[lk + 3][lm] = bv.w;
        __syncthreads();
        #pragma unroll
        for (int kk = 0; kk < TKS; kk++) {
            float4 a = *reinterpret_cast<const float4*>(&As[kk][ty * 4]);
            float4 b = *reinterpret_cast<const float4*>(&Bs[kk][tx * 4]);
            float aa[4] = {a.x, a.y, a.z, a.w};
            float bb[4] = {b.x, b.y, b.z, b.w};
            #pragma unroll
            for (int i = 0; i < 4; i++)
                #pragma unroll
                for (int j = 0; j < 4; j++) acc[i][j] += aa[i] * bb[j];
        }
        __syncthreads();
    }

    #pragma unroll
    for (int i = 0; i < 4; i++) {
        int m = m0 + ty * 4 + i;
        if (m < cnt) {
            float4 o = make_float4(acc[i][0], acc[i][1], acc[i][2], acc[i][3]);
            *reinterpret_cast<float4*>(&d_y[(size_t)(base + m) * HD + n0 + tx * 4]) = o;
        }
    }
}

// out[t][h] = w0 * y[slot0][h] + w1 * y[slot1][h]
__global__ void combine_kernel(float* __restrict__ out) {
    int idx = blockIdx.x * blockDim.x + threadIdx.x; // over TT*HD/4
    if (idx >= TT * (HD / 4)) return;
    int t  = idx / (HD / 4);
    int h4 = (idx % (HD / 4)) * 4;
    int s0 = d_slot[t * 2 + 0], s1 = d_slot[t * 2 + 1];
    float w0 = d_wgt[t * 2 + 0], w1 = d_wgt[t * 2 + 1];
    float4 y0 = *reinterpret_cast<const float4*>(&d_y[(size_t)s0 * HD + h4]);
    float4 y1 = *reinterpret_cast<const float4*>(&d_y[(size_t)s1 * HD + h4]);
    float4 o;
    o.x = w0 * y0.x + w1 * y1.x;
    o.y = w0 * y0.y + w1 * y1.y;
    o.z = w0 * y0.z + w1 * y1.z;
    o.w = w0 * y0.w + w1 * y1.w;
    *reinterpret_cast<float4*>(&out[(size_t)t * HD + h4]) = o;
}

// ---------------- launch ----------------
extern "C" void kernel_launch(void* const* d_in, const int* in_sizes, int n_in,
                              void* d_out, int out_size) {
    const float* x   = (const float*)d_in[0];  // [T, H]
    const float* gw  = (const float*)d_in[1];  // [E, H]
    const float* w1  = (const float*)d_in[2];  // [E, F, H]
    const float* w2  = (const float*)d_in[3];  // [E, H, F]
    const float* w3  = (const float*)d_in[4];  // [E, F, H]
    float* out       = (float*)d_out;          // [T*H] followed by logits [T*E]
    float* logits    = out + (size_t)TT * HD;

    zero_counters_kernel<<<1, 32>>>();
    router_kernel<<<TT, 256>>>(x, gw, logits);
    offsets_kernel<<<1, 32>>>();
    assign_kernel<<<(TT + 255) / 256, 256>>>();

    dim3 g1(FD / TN, TT / TM, NE);   // (64, 64, 8), dead tiles early-exit
    gemm1_kernel<<<g1, 256>>>(x, w1, w3);

    dim3 g2(HD / TN, TT / TM, NE);   // (16, 64, 8)
    gemm2_kernel<<<g2, 256>>>(w2);

    combine_kernel<<<(TT * (HD / 4) + 255) / 256, 256>>>(out);
}

// round 6
// speedup vs baseline: 3.8674x; 3.8674x over previous
#include <cuda_runtime.h>
#include <math.h>
#include <stdint.h>

// Problem constants (fixed by the dataset)
#define TT   4096          // tokens = B*S
#define HD   1024          // hidden
#define FD   4096          // ffn dim
#define NE   8             // experts
#define KSEL 2             // top-k
#define NSLOTS (TT * KSEL) // 8192 token-expert pairs

// ---------------- static scratch (no allocations allowed) ----------------
__device__ int   d_count[NE];
__device__ int   d_fill[NE];
__device__ int   d_offset[NE];
__device__ int   d_rows[NSLOTS];          // slot -> token
__device__ int   d_tope[TT * KSEL];       // token -> expert ids
__device__ int   d_slot[TT * KSEL];       // token -> slot ids
__device__ float d_wgt[TT * KSEL];        // token -> combine weights
__device__ float d_inter[(size_t)NSLOTS * FD];  // 128 MB
__device__ float d_y[(size_t)NSLOTS * HD];      // 32 MB

// ---------------- PTX helpers ----------------
__device__ __forceinline__ uint32_t smem_u32(const void* p) {
    uint32_t a;
    asm("{ .reg .u64 t; cvta.to.shared.u64 t, %1; cvt.u32.u64 %0, t; }" : "=r"(a) : "l"(p));
    return a;
}

#define CP16(s, g) \
    asm volatile("cp.async.cg.shared.global [%0], [%1], 16;" :: "r"(s), "l"(g) : "memory")
#define CPCOMMIT() asm volatile("cp.async.commit_group;" ::: "memory")
#define CPWAIT1()  asm volatile("cp.async.wait_group 1;" ::: "memory")
#define CPWAIT0()  asm volatile("cp.async.wait_group 0;" ::: "memory")

// round-to-nearest tf32 conversion (unbiased — truncation would bias results low)
__device__ __forceinline__ uint32_t tf32r(float f) {
    uint32_t u;
    asm("cvt.rna.tf32.f32 %0, %1;" : "=r"(u) : "f"(f));
    return u;
}

// D += A*B, m16n8k8 tf32 (HMMA path, works on plain sm_103 target)
__device__ __forceinline__ void mma8(float* c, uint32_t a0, uint32_t a1, uint32_t a2,
                                     uint32_t a3, uint32_t b0, uint32_t b1) {
    asm volatile(
        "mma.sync.aligned.m16n8k8.row.col.f32.tf32.tf32.f32 "
        "{%0,%1,%2,%3}, {%4,%5,%6,%7}, {%8,%9}, {%0,%1,%2,%3};"
        : "+f"(c[0]), "+f"(c[1]), "+f"(c[2]), "+f"(c[3])
        : "r"(a0), "r"(a1), "r"(a2), "r"(a3), "r"(b0), "r"(b1));
}

__device__ __forceinline__ float silu_mul(float v, float g) {
    return v / (1.f + __expf(-v)) * g;
}

// ---------------- routing kernels (correctness-proven) ----------------

__global__ void zero_counters_kernel() {
    int i = threadIdx.x;
    if (i < NE) { d_count[i] = 0; d_fill[i] = 0; }
}

__global__ void router_kernel(const float* __restrict__ x,
                              const float* __restrict__ gw,
                              float* __restrict__ logits_out) {
    int t    = blockIdx.x;
    int warp = threadIdx.x >> 5;
    int lane = threadIdx.x & 31;
    const float* xr = x + (size_t)t * HD;
    const float* gr = gw + (size_t)warp * HD;
    float s = 0.f;
    #pragma unroll 8
    for (int i = lane; i < HD; i += 32) s += xr[i] * gr[i];
    #pragma unroll
    for (int o = 16; o; o >>= 1) s += __shfl_xor_sync(0xffffffffu, s, o);
    __shared__ float sl[NE];
    if (lane == 0) sl[warp] = s;
    __syncthreads();
    if (threadIdx.x < NE) logits_out[(size_t)t * NE + threadIdx.x] = sl[threadIdx.x];
    if (threadIdx.x == 0) {
        float mx = sl[0];
        #pragma unroll
        for (int e = 1; e < NE; e++) mx = fmaxf(mx, sl[e]);
        float p[NE];
        #pragma unroll
        for (int e = 0; e < NE; e++) p[e] = expf(sl[e] - mx);
        int e0 = 0;
        #pragma unroll
        for (int e = 1; e < NE; e++) if (p[e] > p[e0]) e0 = e;
        int e1 = (e0 == 0) ? 1 : 0;
        #pragma unroll
        for (int e = 0; e < NE; e++) { if (e == e0) continue; if (p[e] > p[e1]) e1 = e; }
        float w0 = p[e0], w1 = p[e1];
        float ws = w0 + w1;
        w0 /= ws; w1 /= ws;
        d_tope[t * 2 + 0] = e0; d_tope[t * 2 + 1] = e1;
        d_wgt[t * 2 + 0] = w0;  d_wgt[t * 2 + 1] = w1;
        atomicAdd(&d_count[e0], 1);
        atomicAdd(&d_count[e1], 1);
    }
}

__global__ void offsets_kernel() {
    if (threadIdx.x == 0) {
        int acc = 0;
        #pragma unroll
        for (int e = 0; e < NE; e++) { d_offset[e] = acc; acc += d_count[e]; }
    }
}

__global__ void assign_kernel() {
    int t = blockIdx.x * blockDim.x + threadIdx.x;
    if (t >= TT) return;
    #pragma unroll
    for (int k = 0; k < KSEL; k++) {
        int e = d_tope[t * 2 + k];
        int pos = atomicAdd(&d_fill[e], 1);
        int s = d_offset[e] + pos;
        d_rows[s] = t;
        d_slot[t * 2 + k] = s;
    }
}

// =================== GEMM1: tf32 mma.sync, fused SiLU·mul =================
// Block tile 128(M slots) x 64(N ffn), BK=16, 3-stage cp.async, 256 thr.
// 8 warps in 4x2 grid, warp tile 32x32, dual accumulators (w1 & w3).
#define ASTR 20                         // padded float stride (16B-aligned, conflict-free)
#define G1_STG 20480                    // 128*20*4 + 2*64*20*4
#define G1_B1O 10240
#define G1_B3O 15360
#define G1_SMEM (3 * G1_STG + 512)
#define G1_NKS  (HD / 16)

__device__ __forceinline__ void g1_load(char* smem, uint32_t sbase, int st, int k0, int tid,
                                        const float* __restrict__ x,
                                        const int* __restrict__ tok,
                                        const float* __restrict__ W1,
                                        const float* __restrict__ W3) {
    uint32_t ab = sbase + (uint32_t)st * G1_STG;
    #pragma unroll
    for (int t = 0; t < 2; t++) {                 // A: 128 rows x 16 floats
        int c = tid + t * 256;
        int row = c >> 2, q = c & 3;
        CP16(ab + (uint32_t)(row * ASTR + q * 4) * 4,
             x + (size_t)tok[row] * HD + k0 + q * 4);
    }
    {
        int row = tid >> 2, q = tid & 3;          // B1/B3: 64 rows x 16 floats each
        CP16(ab + G1_B1O + (uint32_t)(row * ASTR + q * 4) * 4,
             W1 + (size_t)row * HD + k0 + q * 4);
        CP16(ab + G1_B3O + (uint32_t)(row * ASTR + q * 4) * 4,
             W3 + (size_t)row * HD + k0 + q * 4);
    }
    CPCOMMIT();
}

__global__ void __launch_bounds__(256, 2)
gemm1_mma(const float* __restrict__ x,
          const float* __restrict__ w1,
          const float* __restrict__ w3) {
    int e  = blockIdx.z;
    int nt = blockIdx.x;
    int m0 = blockIdx.y * 128;
    int cnt = d_count[e];
    if (m0 >= cnt) return;
    int base = d_offset[e];

    extern __shared__ char smem[];
    uint32_t sbase = smem_u32(smem);
    int* tok = (int*)(smem + 3 * G1_STG);

    int tid = threadIdx.x;
    int wid = tid >> 5, lane = tid & 31;
    int wm = wid & 3, wn = wid >> 2;       // 4x2 warp grid
    int gid = lane >> 2, tig = lane & 3;

    if (tid < 128) {
        int m = m0 + tid;
        tok[tid] = d_rows[base + (m < cnt ? m : cnt - 1)];
    }
    __syncthreads();

    const float* W1 = w1 + (size_t)e * FD * HD + (size_t)(nt * 64) * HD;
    const float* W3 = w3 + (size_t)e * FD * HD + (size_t)(nt * 64) * HD;

    float acc1[2][4][4], acc3[2][4][4];
    #pragma unroll
    for (int i = 0; i < 2; i++)
        #pragma unroll
        for (int j = 0; j < 4; j++)
            #pragma unroll
            for (int k = 0; k < 4; k++) { acc1[i][j][k] = 0.f; acc3[i][j][k] = 0.f; }

    g1_load(smem, sbase, 0,  0, tid, x, tok, W1, W3);
    g1_load(smem, sbase, 1, 16, tid, x, tok, W1, W3);

    for (int ks = 0; ks < G1_NKS; ks++) {
        if (ks + 1 < G1_NKS) CPWAIT1(); else CPWAIT0();
        __syncthreads();
        if (ks + 2 < G1_NKS)
            g1_load(smem, sbase, (ks + 2) % 3, (ks + 2) * 16, tid, x, tok, W1, W3);

        int st = ks % 3;
        const float* fA  = (const float*)(smem + (size_t)st * G1_STG);
        const float* fB1 = (const float*)(smem + (size_t)st * G1_STG + G1_B1O);
        const float* fB3 = (const float*)(smem + (size_t)st * G1_STG + G1_B3O);

        #pragma unroll
        for (int k8 = 0; k8 < 2; k8++) {
            int kk = k8 * 8;
            uint32_t a[2][4];
            #pragma unroll
            for (int mf = 0; mf < 2; mf++) {
                int r = wm * 32 + mf * 16 + gid;
                a[mf][0] = tf32r(fA[r * ASTR + kk + tig]);
                a[mf][1] = tf32r(fA[(r + 8) * ASTR + kk + tig]);
                a[mf][2] = tf32r(fA[r * ASTR + kk + tig + 4]);
                a[mf][3] = tf32r(fA[(r + 8) * ASTR + kk + tig + 4]);
            }
            #pragma unroll
            for (int nf = 0; nf < 4; nf++) {
                int n = wn * 32 + nf * 8 + gid;
                uint32_t b10 = tf32r(fB1[n * ASTR + kk + tig]);
                uint32_t b11 = tf32r(fB1[n * ASTR + kk + tig + 4]);
                uint32_t b30 = tf32r(fB3[n * ASTR + kk + tig]);
                uint32_t b31 = tf32r(fB3[n * ASTR + kk + tig + 4]);
                #pragma unroll
                for (int mf = 0; mf < 2; mf++) {
                    mma8(acc1[mf][nf], a[mf][0], a[mf][1], a[mf][2], a[mf][3], b10, b11);
                    mma8(acc3[mf][nf], a[mf][0], a[mf][1], a[mf][2], a[mf][3], b30, b31);
                }
            }
        }
        __syncthreads();
    }

    // fused SiLU(h1)*h3 epilogue -> d_inter
    #pragma unroll
    for (int mf = 0; mf < 2; mf++) {
        int r = wm * 32 + mf * 16 + gid;
        #pragma unroll
        for (int nf = 0; nf < 4; nf++) {
            int n = nt * 64 + wn * 32 + nf * 8 + tig * 2;
            if (m0 + r < cnt) {
                float2 o;
                o.x = silu_mul(acc1[mf][nf][0], acc3[mf][nf][0]);
                o.y = silu_mul(acc1[mf][nf][1], acc3[mf][nf][1]);
                *reinterpret_cast<float2*>(&d_inter[(size_t)(base + m0 + r) * FD + n]) = o;
            }
            if (m0 + r + 8 < cnt) {
                float2 o;
                o.x = silu_mul(acc1[mf][nf][2], acc3[mf][nf][2]);
                o.y = silu_mul(acc1[mf][nf][3], acc3[mf][nf][3]);
                *reinterpret_cast<float2*>(&d_inter[(size_t)(base + m0 + r + 8) * FD + n]) = o;
            }
        }
    }
}

// =================== GEMM2: tf32 mma.sync ================================
// Block tile 128(M) x 128(N hidden), BK=16, 3-stage, 256 thr.
// 8 warps in 2x4 grid, warp tile 64x32.
#define G2_STG 20480                    // 2 * 128*20*4
#define G2_BO  10240
#define G2_SMEM (3 * G2_STG)
#define G2_NKS  (FD / 16)

__device__ __forceinline__ void g2_load(uint32_t sbase, int st, int k0, int tid,
                                        int base, int m0, int cnt,
                                        const float* __restrict__ W2) {
    uint32_t ab = sbase + (uint32_t)st * G2_STG;
    #pragma unroll
    for (int t = 0; t < 2; t++) {
        int c = tid + t * 256;
        int row = c >> 2, q = c & 3;
        int rg = m0 + row; if (rg >= cnt) rg = cnt - 1;
        CP16(ab + (uint32_t)(row * ASTR + q * 4) * 4,
             d_inter + (size_t)(base + rg) * FD + k0 + q * 4);
        CP16(ab + G2_BO + (uint32_t)(row * ASTR + q * 4) * 4,
             W2 + (size_t)row * FD + k0 + q * 4);
    }
    CPCOMMIT();
}

__global__ void __launch_bounds__(256, 2)
gemm2_mma(const float* __restrict__ w2) {
    int e  = blockIdx.z;
    int nt = blockIdx.x;
    int m0 = blockIdx.y * 128;
    int cnt = d_count[e];
    if (m0 >= cnt) return;
    int base = d_offset[e];

    extern __shared__ char smem[];
    uint32_t sbase = smem_u32(smem);

    int tid = threadIdx.x;
    int wid = tid >> 5, lane = tid & 31;
    int wm = wid & 1, wn = wid >> 1;       // 2x4 warp grid
    int gid = lane >> 2, tig = lane & 3;

    const float* W2 = w2 + (size_t)e * HD * FD + (size_t)(nt * 128) * FD;

    float acc[4][4][4];
    #pragma unroll
    for (int i = 0; i < 4; i++)
        #pragma unroll
        for (int j = 0; j < 4; j++)
            #pragma unroll
            for (int k = 0; k < 4; k++) acc[i][j][k] = 0.f;

    g2_load(sbase, 0,  0, tid, base, m0, cnt, W2);
    g2_load(sbase, 1, 16, tid, base, m0, cnt, W2);

    for (int ks = 0; ks < G2_NKS; ks++) {
        if (ks + 1 < G2_NKS) CPWAIT1(); else CPWAIT0();
        __syncthreads();
        if (ks + 2 < G2_NKS)
            g2_load(sbase, (ks + 2) % 3, (ks + 2) * 16, tid, base, m0, cnt, W2);

        int st = ks % 3;
        const float* fA = (const float*)(smem + (size_t)st * G2_STG);
        const float* fB = (const float*)(smem + (size_t)st * G2_STG + G2_BO);

        #pragma unroll
        for (int k8 = 0; k8 < 2; k8++) {
            int kk = k8 * 8;
            uint32_t a[4][4];
            #pragma unroll
            for (int mf = 0; mf < 4; mf++) {
                int r = wm * 64 + mf * 16 + gid;
                a[mf][0] = tf32r(fA[r * ASTR + kk + tig]);
                a[mf][1] = tf32r(fA[(r + 8) * ASTR + kk + tig]);
                a[mf][2] = tf32r(fA[r * ASTR + kk + tig + 4]);
                a[mf][3] = tf32r(fA[(r + 8) * ASTR + kk + tig + 4]);
            }
            #pragma unroll
            for (int nf = 0; nf < 4; nf++) {
                int n = wn * 32 + nf * 8 + gid;
                uint32_t b0 = tf32r(fB[n * ASTR + kk + tig]);
                uint32_t b1 = tf32r(fB[n * ASTR + kk + tig + 4]);
                #pragma unroll
                for (int mf = 0; mf < 4; mf++)
                    mma8(acc[mf][nf], a[mf][0], a[mf][1], a[mf][2], a[mf][3], b0, b1);
            }
        }
        __syncthreads();
    }

    #pragma unroll
    for (int mf = 0; mf < 4; mf++) {
        int r = wm * 64 + mf * 16 + gid;
        #pragma unroll
        for (int nf = 0; nf < 4; nf++) {
            int n = nt * 128 + wn * 32 + nf * 8 + tig * 2;
            if (m0 + r < cnt) {
                float2 o = make_float2(acc[mf][nf][0], acc[mf][nf][1]);
                *reinterpret_cast<float2*>(&d_y[(size_t)(base + m0 + r) * HD + n]) = o;
            }
            if (m0 + r + 8 < cnt) {
                float2 o = make_float2(acc[mf][nf][2], acc[mf][nf][3]);
                *reinterpret_cast<float2*>(&d_y[(size_t)(base + m0 + r + 8) * HD + n]) = o;
            }
        }
    }
}

// ---------------- combine ----------------
__global__ void combine_kernel(float* __restrict__ out) {
    int idx = blockIdx.x * blockDim.x + threadIdx.x;
    if (idx >= TT * (HD / 4)) return;
    int t  = idx / (HD / 4);
    int h4 = (idx % (HD / 4)) * 4;
    int s0 = d_slot[t * 2 + 0], s1 = d_slot[t * 2 + 1];
    float w0 = d_wgt[t * 2 + 0], w1 = d_wgt[t * 2 + 1];
    float4 y0 = *reinterpret_cast<const float4*>(&d_y[(size_t)s0 * HD + h4]);
    float4 y1 = *reinterpret_cast<const float4*>(&d_y[(size_t)s1 * HD + h4]);
    float4 o;
    o.x = w0 * y0.x + w1 * y1.x;
    o.y = w0 * y0.y + w1 * y1.y;
    o.z = w0 * y0.z + w1 * y1.z;
    o.w = w0 * y0.w + w1 * y1.w;
    *reinterpret_cast<float4*>(&out[(size_t)t * HD + h4]) = o;
}

// ---------------- launch ----------------
extern "C" void kernel_launch(void* const* d_in, const int* in_sizes, int n_in,
                              void* d_out, int out_size) {
    const float* x   = (const float*)d_in[0];  // [T, H]
    const float* gw  = (const float*)d_in[1];  // [E, H]
    const float* w1  = (const float*)d_in[2];  // [E, F, H]
    const float* w2  = (const float*)d_in[3];  // [E, H, F]
    const float* w3  = (const float*)d_in[4];  // [E, F, H]
    float* out       = (float*)d_out;          // [T*H] then logits [T*E]
    float* logits    = out + (size_t)TT * HD;

    cudaFuncSetAttribute(gemm1_mma, cudaFuncAttributeMaxDynamicSharedMemorySize, G1_SMEM);
    cudaFuncSetAttribute(gemm2_mma, cudaFuncAttributeMaxDynamicSharedMemorySize, G2_SMEM);

    zero_counters_kernel<<<1, 32>>>();
    router_kernel<<<TT, 256>>>(x, gw, logits);
    offsets_kernel<<<1, 32>>>();
    assign_kernel<<<(TT + 255) / 256, 256>>>();

    dim3 g1(FD / 64, TT / 128, NE);    // (64, 32, 8), dead tiles early-exit
    gemm1_mma<<<g1, 256, G1_SMEM>>>(x, w1, w3);

    dim3 g2(HD / 128, TT / 128, NE);   // (8, 32, 8)
    gemm2_mma<<<g2, 256, G2_SMEM>>>(w2);

    combine_kernel<<<(TT * (HD / 4) + 255) / 256, 256>>>(out);
}